// round 5
// baseline (speedup 1.0000x reference)
#include <cuda_runtime.h>
#include <stdint.h>

// Problem constants (fixed by the dataset)
#define NN 100000      // nodes
#define EE 1600000     // edges
#define F0 128
#define F1 64
#define F2 40

// ---------------- scratch (static device globals; allocation-free) ----------
__device__ __align__(16) float g_h1s [NN * F1];   // 25.6 MB  (x @ W1) * invsqrt[row]
__device__ __align__(16) float g_out1[NN * F1];   // 25.6 MB  relu(invsqrt*(sum+self))
__device__ __align__(16) float g_h2s [NN * F2];   // 16 MB    (out1 @ W2) * invsqrt[row]
__device__ int   g_deg[NN];
__device__ int   g_off[NN + 1];
__device__ int   g_cursor[NN];
__device__ int   g_csr_src[EE];                   // 6.4 MB, edge srcs grouped by dst
__device__ float g_invsqrt[NN];

// ---------------- kernels ---------------------------------------------------

__global__ void zero_kernel() {
    int i = blockIdx.x * blockDim.x + threadIdx.x;
    if (i < NN) g_deg[i] = 0;
}

// Degree histogram over dst; 2 edges per thread for atomic MLP.
__global__ void deg_kernel(const int* __restrict__ dst, int E) {
    int i = (blockIdx.x * blockDim.x + threadIdx.x) * 2;
    if (i + 1 < E) {
        int2 d = *reinterpret_cast<const int2*>(dst + i);
        atomicAdd(&g_deg[d.x], 1);
        atomicAdd(&g_deg[d.y], 1);
    } else if (i < E) {
        atomicAdd(&g_deg[dst[i]], 1);
    }
}

// Single-block exclusive prefix scan of g_deg -> g_off / g_cursor, fused with
// invsqrt computation. 1024 threads, each owns a contiguous chunk of ~98 nodes.
__global__ __launch_bounds__(1024) void prefix_kernel() {
    __shared__ int ssum[1024];
    const int CH = (NN + 1023) / 1024;   // 98
    int t = threadIdx.x;
    int b = t * CH;
    int e = b + CH < NN ? b + CH : NN;
    if (b > NN) b = NN;

    int s = 0;
    for (int i = b; i < e; ++i) s += g_deg[i];
    ssum[t] = s;
    __syncthreads();

    for (int off = 1; off < 1024; off <<= 1) {
        int v = (t >= off) ? ssum[t - off] : 0;
        __syncthreads();
        ssum[t] += v;
        __syncthreads();
    }

    int run = ssum[t] - s;               // exclusive start of this chunk
    for (int i = b; i < e; ++i) {
        g_off[i]    = run;
        g_cursor[i] = run;
        int d = g_deg[i];
        run += d;
        g_invsqrt[i] = rsqrtf((float)(d + 1));
    }
    if (t == 1023) g_off[NN] = ssum[1023];
}

// Fill CSR: group edge srcs by dst via cursor atomics; 2 edges per thread.
__global__ void fill_kernel(const int* __restrict__ src,
                            const int* __restrict__ dst, int E) {
    int i = (blockIdx.x * blockDim.x + threadIdx.x) * 2;
    if (i + 1 < E) {
        int2 d = *reinterpret_cast<const int2*>(dst + i);
        int2 s = *reinterpret_cast<const int2*>(src + i);
        int p0 = atomicAdd(&g_cursor[d.x], 1);
        int p1 = atomicAdd(&g_cursor[d.y], 1);
        g_csr_src[p0] = s.x;
        g_csr_src[p1] = s.y;
    } else if (i < E) {
        int pos = atomicAdd(&g_cursor[dst[i]], 1);
        g_csr_src[pos] = src[i];
    }
}

// h1s = (x @ W1) * invsqrt[row]  (100000x128 @ 128x64), fp32.
// Block: 128 threads = 32 row-groups x 4 col-groups. Thread: 4 rows x 16 cols.
__global__ __launch_bounds__(128) void gemm1_kernel(const float* __restrict__ x,
                                                    const float* __restrict__ W1) {
    __shared__ float sW[F0 * F1];           // 32 KB
    int tid = threadIdx.x;
    for (int i = tid; i < F0 * F1; i += 128) sW[i] = W1[i];
    __syncthreads();

    int rg = tid & 31;
    int cg = tid >> 5;
    int row0 = blockIdx.x * 128 + rg * 4;
    int c0 = cg * 16;

    float acc[4][16];
    #pragma unroll
    for (int r = 0; r < 4; ++r)
        #pragma unroll
        for (int j = 0; j < 16; ++j) acc[r][j] = 0.f;

    const float4* xr[4];
    #pragma unroll
    for (int r = 0; r < 4; ++r) {
        int rr = row0 + r; if (rr >= NN) rr = NN - 1;
        xr[r] = reinterpret_cast<const float4*>(x + (size_t)rr * F0);
    }

    #pragma unroll 4
    for (int k4 = 0; k4 < F0 / 4; ++k4) {
        float4 xv[4];
        #pragma unroll
        for (int r = 0; r < 4; ++r) xv[r] = xr[r][k4];
        #pragma unroll
        for (int kk = 0; kk < 4; ++kk) {
            const float4* w4 = reinterpret_cast<const float4*>(sW + (k4 * 4 + kk) * F1 + c0);
            float4 w0 = w4[0], w1 = w4[1], w2 = w4[2], w3 = w4[3];
            float wv[16] = {w0.x,w0.y,w0.z,w0.w, w1.x,w1.y,w1.z,w1.w,
                            w2.x,w2.y,w2.z,w2.w, w3.x,w3.y,w3.z,w3.w};
            #pragma unroll
            for (int r = 0; r < 4; ++r) {
                float xs = (kk == 0) ? xv[r].x : (kk == 1) ? xv[r].y
                         : (kk == 2) ? xv[r].z : xv[r].w;
                #pragma unroll
                for (int j = 0; j < 16; ++j)
                    acc[r][j] = fmaf(xs, wv[j], acc[r][j]);
            }
        }
    }

    #pragma unroll
    for (int r = 0; r < 4; ++r) {
        int rr = row0 + r;
        if (rr < NN) {
            float sc = g_invsqrt[rr];
            float4* out = reinterpret_cast<float4*>(g_h1s + (size_t)rr * F1 + c0);
            #pragma unroll
            for (int j = 0; j < 4; ++j)
                out[j] = make_float4(acc[r][4*j]*sc, acc[r][4*j+1]*sc,
                                     acc[r][4*j+2]*sc, acc[r][4*j+3]*sc);
        }
    }
}

// Layer-1 aggregation: out1 = relu(invsqrt[d] * (sum_{s in N(d)} h1s[s] + h1s[d])).
// One warp per node; lane owns feature pair [2*lane, 2*lane+1]. 4 edges in flight.
__global__ __launch_bounds__(256) void agg1_kernel() {
    int node = (blockIdx.x * 256 + threadIdx.x) >> 5;
    int lane = threadIdx.x & 31;
    if (node >= NN) return;

    int beg = g_off[node];
    int end = g_off[node + 1];
    float inv_d = g_invsqrt[node];

    const float2* h1f = reinterpret_cast<const float2*>(g_h1s);
    float2 a0 = make_float2(0.f, 0.f);
    float2 a1 = make_float2(0.f, 0.f);

    int e = beg;
    for (; e + 3 < end; e += 4) {
        int s0 = g_csr_src[e];
        int s1 = g_csr_src[e + 1];
        int s2 = g_csr_src[e + 2];
        int s3 = g_csr_src[e + 3];
        float2 v0 = h1f[(size_t)s0 * 32 + lane];
        float2 v1 = h1f[(size_t)s1 * 32 + lane];
        float2 v2 = h1f[(size_t)s2 * 32 + lane];
        float2 v3 = h1f[(size_t)s3 * 32 + lane];
        a0.x += v0.x; a0.y += v0.y;
        a1.x += v1.x; a1.y += v1.y;
        a0.x += v2.x; a0.y += v2.y;
        a1.x += v3.x; a1.y += v3.y;
    }
    for (; e < end; ++e) {
        int s0 = g_csr_src[e];
        float2 v0 = h1f[(size_t)s0 * 32 + lane];
        a0.x += v0.x; a0.y += v0.y;
    }

    float2 h = h1f[(size_t)node * 32 + lane];
    float2 o;
    o.x = fmaxf(inv_d * (a0.x + a1.x + h.x), 0.f);
    o.y = fmaxf(inv_d * (a0.y + a1.y + h.y), 0.f);
    reinterpret_cast<float2*>(g_out1)[(size_t)node * 32 + lane] = o;
}

// h2s = (out1 @ W2) * invsqrt[row] (64 -> 40). Thread per row, W2 in SMEM.
__global__ __launch_bounds__(256) void gemm2_kernel(const float* __restrict__ W2) {
    __shared__ float sW[F1 * F2];           // 10.25 KB
    int tid = threadIdx.x;
    for (int i = tid; i < F1 * F2; i += 256) sW[i] = W2[i];
    __syncthreads();

    int row = blockIdx.x * 256 + tid;
    if (row >= NN) return;

    float acc[F2];
    #pragma unroll
    for (int j = 0; j < F2; ++j) acc[j] = 0.f;

    const float4* orow = reinterpret_cast<const float4*>(g_out1 + (size_t)row * F1);
    #pragma unroll 2
    for (int k4 = 0; k4 < F1 / 4; ++k4) {
        float4 ov = orow[k4];
        float oa[4] = {ov.x, ov.y, ov.z, ov.w};
        #pragma unroll
        for (int kk = 0; kk < 4; ++kk) {
            float os = oa[kk];
            const float4* w4 = reinterpret_cast<const float4*>(sW + (k4 * 4 + kk) * F2);
            #pragma unroll
            for (int j = 0; j < F2 / 4; ++j) {
                float4 w = w4[j];
                acc[4*j+0] = fmaf(os, w.x, acc[4*j+0]);
                acc[4*j+1] = fmaf(os, w.y, acc[4*j+1]);
                acc[4*j+2] = fmaf(os, w.z, acc[4*j+2]);
                acc[4*j+3] = fmaf(os, w.w, acc[4*j+3]);
            }
        }
    }
    float sc = g_invsqrt[row];
    float4* out = reinterpret_cast<float4*>(g_h2s + (size_t)row * F2);
    #pragma unroll
    for (int j = 0; j < F2 / 4; ++j)
        out[j] = make_float4(acc[4*j]*sc, acc[4*j+1]*sc, acc[4*j+2]*sc, acc[4*j+3]*sc);
}

// Layer-2 aggregation -> d_out: out = relu(invsqrt[d] * (sum h2s[s] + h2s[d])).
// One warp per node; lane owns feature `lane`, + feature 32+lane if lane<8.
__global__ __launch_bounds__(256) void agg2_kernel(float* __restrict__ out) {
    int node = (blockIdx.x * 256 + threadIdx.x) >> 5;
    int lane = threadIdx.x & 31;
    if (node >= NN) return;

    int beg = g_off[node];
    int end = g_off[node + 1];
    float inv_d = g_invsqrt[node];
    bool hi = (lane < 8);

    float aa0 = 0.f, ab0 = 0.f;
    float aa1 = 0.f, ab1 = 0.f;

    int e = beg;
    for (; e + 3 < end; e += 4) {
        int s0 = g_csr_src[e];
        int s1 = g_csr_src[e + 1];
        int s2 = g_csr_src[e + 2];
        int s3 = g_csr_src[e + 3];
        const float* r0 = g_h2s + (size_t)s0 * F2;
        const float* r1 = g_h2s + (size_t)s1 * F2;
        const float* r2 = g_h2s + (size_t)s2 * F2;
        const float* r3 = g_h2s + (size_t)s3 * F2;
        float va0 = r0[lane], va1 = r1[lane], va2 = r2[lane], va3 = r3[lane];
        float vb0 = hi ? r0[32 + lane] : 0.f;
        float vb1 = hi ? r1[32 + lane] : 0.f;
        float vb2 = hi ? r2[32 + lane] : 0.f;
        float vb3 = hi ? r3[32 + lane] : 0.f;
        aa0 += va0 + va2; aa1 += va1 + va3;
        ab0 += vb0 + vb2; ab1 += vb1 + vb3;
    }
    for (; e < end; ++e) {
        int s0 = g_csr_src[e];
        const float* r0 = g_h2s + (size_t)s0 * F2;
        aa0 += r0[lane];
        if (hi) ab0 += r0[32 + lane];
    }

    const float* hrow = g_h2s + (size_t)node * F2;
    float* orow = out + (size_t)node * F2;
    orow[lane] = fmaxf(inv_d * (aa0 + aa1 + hrow[lane]), 0.f);
    if (hi)
        orow[32 + lane] = fmaxf(inv_d * (ab0 + ab1 + hrow[32 + lane]), 0.f);
}

// ---------------- launch ----------------------------------------------------
extern "C" void kernel_launch(void* const* d_in, const int* in_sizes, int n_in,
                              void* d_out, int out_size) {
    const float* x  = (const float*)d_in[0];   // [N,128]
    const int*   ei = (const int*)  d_in[1];   // [2,E]
    const float* W1 = (const float*)d_in[2];   // [128,64]
    const float* W2 = (const float*)d_in[3];   // [64,40]
    float* out = (float*)d_out;

    int E = in_sizes[1] / 2;
    const int* src = ei;
    const int* dst = ei + E;

    // CSR build (by dst) + norms
    zero_kernel  <<<(NN + 255) / 256, 256>>>();
    deg_kernel   <<<(E/2 + 255) / 256, 256>>>(dst, E);
    prefix_kernel<<<1, 1024>>>();
    fill_kernel  <<<(E/2 + 255) / 256, 256>>>(src, dst, E);

    // layer 1
    gemm1_kernel <<<(NN + 127) / 128, 128>>>(x, W1);     // h1s = (x @ W1) * invsqrt
    agg1_kernel  <<<(NN * 32 + 255) / 256, 256>>>();     // out1

    // layer 2
    gemm2_kernel <<<(NN + 255) / 256, 256>>>(W2);        // h2s = (out1 @ W2) * invsqrt
    agg2_kernel  <<<(NN * 32 + 255) / 256, 256>>>(out);  // final
}

// round 7
// speedup vs baseline: 1.4325x; 1.4325x over previous
#include <cuda_runtime.h>
#include <stdint.h>

// Problem constants (fixed by the dataset)
#define NN 100000      // nodes
#define F0 128
#define F1 64
#define F2 40

// ---------------- scratch (static device globals; allocation-free) ----------
__device__ __align__(16) float g_h1s [NN * F1];   // (x @ W1) * invsqrt[row]
__device__ __align__(16) float g_agg1[NN * F1];   // sum of h1s[src] per dst
__device__ __align__(16) float g_h2s [NN * F2];   // (out1 @ W2) * invsqrt[row]
__device__ __align__(16) float g_agg2[NN * F2];   // sum of h2s[src] per dst
__device__ int   g_deg[NN];
__device__ float g_invsqrt[NN];

// ---------------- helpers ---------------------------------------------------
__device__ __forceinline__ void red_add_v4(float* addr, float4 v) {
    asm volatile("red.global.add.v4.f32 [%0], {%1, %2, %3, %4};"
                 :: "l"(addr), "f"(v.x), "f"(v.y), "f"(v.z), "f"(v.w)
                 : "memory");
}

// ---------------- kernels ---------------------------------------------------

// Zero agg1, agg2 (as float4) and deg counters. Grid-stride.
__global__ void zero_kernel() {
    const int n1 = NN * (F1 / 4);          // 1.6M float4
    const int n2 = NN * (F2 / 4);          // 1.0M float4
    float4 z = make_float4(0.f, 0.f, 0.f, 0.f);
    for (int i = blockIdx.x * blockDim.x + threadIdx.x; i < n1 + n2;
         i += gridDim.x * blockDim.x) {
        if (i < n1) reinterpret_cast<float4*>(g_agg1)[i] = z;
        else        reinterpret_cast<float4*>(g_agg2)[i - n1] = z;
        if (i < NN) g_deg[i] = 0;
    }
}

// Degree histogram over dst (self-loop added later as +1).
__global__ void deg_kernel(const int* __restrict__ dst, int E) {
    int i = blockIdx.x * blockDim.x + threadIdx.x;
    if (i < E) atomicAdd(&g_deg[dst[i]], 1);
}

__global__ void invsqrt_kernel() {
    int i = blockIdx.x * blockDim.x + threadIdx.x;
    if (i < NN) g_invsqrt[i] = rsqrtf((float)(g_deg[i] + 1));
}

// h1s = (x @ W1) * invsqrt[row]   (100000x128 @ 128x64), fp32.
// Tiled GEMM: block = 256 threads computes 64 rows x 64 cols, 4x4 micro-tile.
// k dimension processed in 2 chunks of 64 to stay under 48 KB static smem:
// sX chunk (64k x 64rows, pitch 68) = 17.4 KB + sW chunk (64x64) = 16 KB.
__global__ __launch_bounds__(256) void gemm1_kernel(const float* __restrict__ x,
                                                    const float* __restrict__ W1) {
    __shared__ float sX[64][68];            // [k_local][row], padded pitch
    __shared__ float sW[64 * F1];           // [k_local][col] chunk, 16 KB
    int tid = threadIdx.x;
    int row0 = blockIdx.x * 64;

    int tx = tid & 15;                      // col group: cols tx*4..+3
    int ty = tid >> 4;                      // row group: rows ty*4..+3

    float acc[4][4];
    #pragma unroll
    for (int r = 0; r < 4; ++r)
        #pragma unroll
        for (int c = 0; c < 4; ++c) acc[r][c] = 0.f;

    #pragma unroll
    for (int kc = 0; kc < 2; ++kc) {
        int k0 = kc * 64;

        // load W1 chunk: rows k0..k0+63, all 64 cols = 1024 float4
        const float4* w4g = reinterpret_cast<const float4*>(W1 + k0 * F1);
        #pragma unroll
        for (int i = 0; i < 4; ++i)
            reinterpret_cast<float4*>(sW)[tid + i * 256] = w4g[tid + i * 256];

        // load x chunk (64 rows x 64 k = 1024 float4), transpose into sX[k][row]
        #pragma unroll
        for (int i = 0; i < 4; ++i) {
            int idx = tid + i * 256;        // 0..1023
            int r   = idx >> 4;             // 0..63 (16 float4 per row-chunk)
            int k4  = idx & 15;             // float4 index along k within chunk
            int rr = row0 + r; if (rr >= NN) rr = NN - 1;
            float4 v = reinterpret_cast<const float4*>(
                           x + (size_t)rr * F0 + k0)[k4];
            sX[k4 * 4 + 0][r] = v.x;
            sX[k4 * 4 + 1][r] = v.y;
            sX[k4 * 4 + 2][r] = v.z;
            sX[k4 * 4 + 3][r] = v.w;
        }
        __syncthreads();

        #pragma unroll 4
        for (int k = 0; k < 64; ++k) {
            float4 xv = *reinterpret_cast<const float4*>(&sX[k][ty * 4]);
            float4 wv = *reinterpret_cast<const float4*>(&sW[k * F1 + tx * 4]);
            float xa[4] = {xv.x, xv.y, xv.z, xv.w};
            float wa[4] = {wv.x, wv.y, wv.z, wv.w};
            #pragma unroll
            for (int r = 0; r < 4; ++r)
                #pragma unroll
                for (int c = 0; c < 4; ++c)
                    acc[r][c] = fmaf(xa[r], wa[c], acc[r][c]);
        }
        __syncthreads();
    }

    #pragma unroll
    for (int r = 0; r < 4; ++r) {
        int rr = row0 + ty * 4 + r;
        if (rr < NN) {
            float sc = g_invsqrt[rr];
            *reinterpret_cast<float4*>(g_h1s + (size_t)rr * F1 + tx * 4) =
                make_float4(acc[r][0] * sc, acc[r][1] * sc,
                            acc[r][2] * sc, acc[r][3] * sc);
        }
    }
}

// Layer-1 scatter: agg1[dst] += h1s[src].  8 threads/edge, 2 float4 each.
__global__ __launch_bounds__(256) void scatter1_kernel(const int* __restrict__ src,
                                                       const int* __restrict__ dst, int E) {
    int i = blockIdx.x * blockDim.x + threadIdx.x;
    int total = E * 8;
    if (i >= total) return;
    int e = i >> 3;
    int c = (i & 7) * 2;           // float4 lane pair: c, c+1
    int s = __ldg(src + e);
    int d = __ldg(dst + e);
    const float4* hp = reinterpret_cast<const float4*>(g_h1s + (size_t)s * F1) + c;
    float*        ap = g_agg1 + (size_t)d * F1 + c * 4;
    float4 v0 = hp[0];
    float4 v1 = hp[1];
    red_add_v4(ap,     v0);
    red_add_v4(ap + 4, v1);
}

// out1 = relu(invsqrt_d * (agg1 + h1s));  h2s = (out1 @ W2) * invsqrt_d.
__global__ __launch_bounds__(128) void fuse2_kernel(const float* __restrict__ W2) {
    __shared__ float sW[F1 * F2];           // 10.25 KB
    int tid = threadIdx.x;
    for (int i = tid; i < F1 * F2; i += 128) sW[i] = W2[i];
    __syncthreads();

    int row = blockIdx.x * 128 + tid;
    if (row >= NN) return;

    float inv_d = g_invsqrt[row];

    float o[F1];
    const float4* ag = reinterpret_cast<const float4*>(g_agg1 + (size_t)row * F1);
    const float4* hr = reinterpret_cast<const float4*>(g_h1s  + (size_t)row * F1);
    #pragma unroll
    for (int j = 0; j < F1 / 4; ++j) {
        float4 a = ag[j];
        float4 h = hr[j];
        o[4*j+0] = fmaxf(inv_d * (a.x + h.x), 0.f);
        o[4*j+1] = fmaxf(inv_d * (a.y + h.y), 0.f);
        o[4*j+2] = fmaxf(inv_d * (a.z + h.z), 0.f);
        o[4*j+3] = fmaxf(inv_d * (a.w + h.w), 0.f);
    }

    float acc[F2];
    #pragma unroll
    for (int j = 0; j < F2; ++j) acc[j] = 0.f;

    #pragma unroll 4
    for (int k = 0; k < F1; ++k) {
        float ov = o[k];
        const float4* w4 = reinterpret_cast<const float4*>(sW + k * F2);
        #pragma unroll
        for (int j = 0; j < F2 / 4; ++j) {
            float4 w = w4[j];
            acc[4*j+0] = fmaf(ov, w.x, acc[4*j+0]);
            acc[4*j+1] = fmaf(ov, w.y, acc[4*j+1]);
            acc[4*j+2] = fmaf(ov, w.z, acc[4*j+2]);
            acc[4*j+3] = fmaf(ov, w.w, acc[4*j+3]);
        }
    }
    float4* out = reinterpret_cast<float4*>(g_h2s + (size_t)row * F2);
    #pragma unroll
    for (int j = 0; j < F2 / 4; ++j)
        out[j] = make_float4(acc[4*j]*inv_d, acc[4*j+1]*inv_d,
                             acc[4*j+2]*inv_d, acc[4*j+3]*inv_d);
}

// Layer-2 scatter: agg2[dst] += h2s[src].  5 threads/edge, 2 float4 each.
__global__ __launch_bounds__(256) void scatter2_kernel(const int* __restrict__ src,
                                                       const int* __restrict__ dst, int E) {
    int i = blockIdx.x * blockDim.x + threadIdx.x;
    int total = E * 5;
    if (i >= total) return;
    int e = i / 5;
    int c = (i - e * 5) * 2;       // float4 lane pair
    int s = __ldg(src + e);
    int d = __ldg(dst + e);
    const float4* hp = reinterpret_cast<const float4*>(g_h2s + (size_t)s * F2) + c;
    float*        ap = g_agg2 + (size_t)d * F2 + c * 4;
    float4 v0 = hp[0];
    float4 v1 = hp[1];
    red_add_v4(ap,     v0);
    red_add_v4(ap + 4, v1);
}

// out = relu(invsqrt_d * (agg2 + h2s))
__global__ __launch_bounds__(256) void final_kernel(float* __restrict__ out) {
    int i = blockIdx.x * blockDim.x + threadIdx.x;
    const int total = NN * (F2 / 4);
    if (i >= total) return;
    int node = i / 10;
    float inv_d = g_invsqrt[node];
    float4 a = reinterpret_cast<const float4*>(g_agg2)[i];
    float4 h = reinterpret_cast<const float4*>(g_h2s)[i];
    float4 r;
    r.x = fmaxf(inv_d * (a.x + h.x), 0.f);
    r.y = fmaxf(inv_d * (a.y + h.y), 0.f);
    r.z = fmaxf(inv_d * (a.z + h.z), 0.f);
    r.w = fmaxf(inv_d * (a.w + h.w), 0.f);
    reinterpret_cast<float4*>(out)[i] = r;
}

// ---------------- launch ----------------------------------------------------
extern "C" void kernel_launch(void* const* d_in, const int* in_sizes, int n_in,
                              void* d_out, int out_size) {
    const float* x  = (const float*)d_in[0];   // [N,128]
    const int*   ei = (const int*)  d_in[1];   // [2,E]
    const float* W1 = (const float*)d_in[2];   // [128,64]
    const float* W2 = (const float*)d_in[3];   // [64,40]
    float* out = (float*)d_out;

    int E = in_sizes[1] / 2;
    const int* src = ei;
    const int* dst = ei + E;

    // 1. zero scratch
    zero_kernel<<<2048, 256>>>();
    // 2. degree histogram
    deg_kernel<<<(E + 255) / 256, 256>>>(dst, E);
    // 3. inv sqrt
    invsqrt_kernel<<<(NN + 255) / 256, 256>>>();
    // 4. h1s = (x @ W1) * invsqrt   (tiled GEMM, k-chunked)
    gemm1_kernel<<<(NN + 63) / 64, 256>>>(x, W1);
    // 5. layer-1 edge scatter (raw adds of pre-scaled rows)
    scatter1_kernel<<<(E * 8 + 255) / 256, 256>>>(src, dst, E);
    // 6. relu + self term + GEMM2 -> h2s
    fuse2_kernel<<<(NN + 127) / 128, 128>>>(W2);
    // 7. layer-2 edge scatter
    scatter2_kernel<<<(E * 5 + 255) / 256, 256>>>(src, dst, E);
    // 8. final relu -> d_out
    final_kernel<<<(NN * (F2/4) + 255) / 256, 256>>>(out);
}